// round 10
// baseline (speedup 1.0000x reference)
#include <cuda_runtime.h>
#include <cstdint>

// ProgressiveBandHashGrid — warp-per-level, 2 points per thread (ILP for MLP).
// x:[N,3] f32, table:[16,2^19,2] f32, mask:[32] f32, out:[N,32] f32.
// Resolutions (reference fp64): 17 23 31 43 59 81 112 154 213 295 407 562 777
// 1073 1483 2049; dense iff res^3 <= 2^19 -> lv 0..4 dense.
//
// Evidence from rounds 3/5/7: per-thread loads-in-flight beat occupancy.
// Each thread now computes BOTH points' indices, issues all (up to 16) gathers,
// then consumes — point B's loads overlap point A's latency.

#define THREADS 256
#define PTS 64           // points per block: lane and lane+32
#define NWARPS 8
#define TILE_STRIDE 33   // 32 feats + 1 pad
#define TBITS 19
#define TSIZE (1u << TBITS)

__constant__ int c_res[16]  = {17, 23, 31, 43, 59, 81, 112, 154,
                               213, 295, 407, 562, 777, 1073, 1483, 2049};
__constant__ int c_res2[16] = {289, 529, 961, 1849, 3481, 6561, 12544, 23716,
                               45369, 87025, 165649, 315844, 603729, 1151329,
                               2199289, 4198401};
__constant__ int c_dense[16] = {1, 1, 1, 1, 1, 0, 0, 0,
                                0, 0, 0, 0, 0, 0, 0, 0};

// Corner order: [i000,i100, i010,i110, i001,i101, i011,i111] (x-pairs adjacent).
__device__ __forceinline__ void corner_indices(int lv, int res,
                                               float px, float py, float pz,
                                               uint32_t idx[8],
                                               float& wx, float& wy, float& wz)
{
    const float scale = (float)(res - 1);
    const float fx = px * scale, fy = py * scale, fz = pz * scale;
    int cx = __float2int_rd(fx); cx = max(0, min(cx, res - 2));
    int cy = __float2int_rd(fy); cy = max(0, min(cy, res - 2));
    int cz = __float2int_rd(fz); cz = max(0, min(cz, res - 2));
    wx = fx - (float)cx;  wy = fy - (float)cy;  wz = fz - (float)cz;

    if (c_dense[lv]) {                        // warp-uniform branch
        const uint32_t sy = (uint32_t)res;
        const uint32_t sz = (uint32_t)c_res2[lv];
        const uint32_t base = (uint32_t)cx + sy * (uint32_t)cy + sz * (uint32_t)cz;
        idx[0] = base;            idx[1] = base + 1u;
        idx[2] = base + sy;       idx[3] = base + sy + 1u;
        idx[4] = base + sz;       idx[5] = base + sz + 1u;
        idx[6] = base + sy + sz;  idx[7] = base + sy + sz + 1u;
    } else {
        const uint32_t P1 = 2654435761u, P2 = 805459861u;
        const uint32_t M = TSIZE - 1u;
        const uint32_t hx0 = (uint32_t)cx,      hx1 = hx0 + 1u;
        const uint32_t hy0 = (uint32_t)cy * P1, hy1 = hy0 + P1;
        const uint32_t hz0 = (uint32_t)cz * P2, hz1 = hz0 + P2;
        idx[0] = (hx0 ^ hy0 ^ hz0) & M;  idx[1] = (hx1 ^ hy0 ^ hz0) & M;
        idx[2] = (hx0 ^ hy1 ^ hz0) & M;  idx[3] = (hx1 ^ hy1 ^ hz0) & M;
        idx[4] = (hx0 ^ hy0 ^ hz1) & M;  idx[5] = (hx1 ^ hy0 ^ hz1) & M;
        idx[6] = (hx0 ^ hy1 ^ hz1) & M;  idx[7] = (hx1 ^ hy1 ^ hz1) & M;
    }
}

// Load x-corner pair (i0, i1): aligned adjacent -> one 16B load, else two 8B.
__device__ __forceinline__ void load_pair(const float2* __restrict__ tbl,
                                          uint32_t i0, uint32_t i1,
                                          float2& v0, float2& v1)
{
    if ((i0 ^ i1) == 1u) {
        const float4 q = __ldg(reinterpret_cast<const float4*>(tbl) + (i0 >> 1));
        if (i0 & 1u) { v0.x = q.z; v0.y = q.w; v1.x = q.x; v1.y = q.y; }
        else         { v0.x = q.x; v0.y = q.y; v1.x = q.z; v1.y = q.w; }
    } else {
        v0 = __ldg(tbl + i0);
        v1 = __ldg(tbl + i1);
    }
}

__device__ __forceinline__ void trilerp(const float2 v[8],
                                        float wx, float wy, float wz,
                                        float& f0, float& f1)
{
    const float ux = 1.f - wx, uy = 1.f - wy, uz = 1.f - wz;
    const float y0z0 = uy * uz, y1z0 = wy * uz;
    const float y0z1 = uy * wz, y1z1 = wy * wz;
    const float w0 = ux * y0z0, w1 = wx * y0z0;
    const float w2 = ux * y1z0, w3 = wx * y1z0;
    const float w4 = ux * y0z1, w5 = wx * y0z1;
    const float w6 = ux * y1z1, w7 = wx * y1z1;
    f0 = v[0].x * w0;            f1 = v[0].y * w0;
    f0 = fmaf(v[1].x, w1, f0);   f1 = fmaf(v[1].y, w1, f1);
    f0 = fmaf(v[2].x, w2, f0);   f1 = fmaf(v[2].y, w2, f1);
    f0 = fmaf(v[3].x, w3, f0);   f1 = fmaf(v[3].y, w3, f1);
    f0 = fmaf(v[4].x, w4, f0);   f1 = fmaf(v[4].y, w4, f1);
    f0 = fmaf(v[5].x, w5, f0);   f1 = fmaf(v[5].y, w5, f1);
    f0 = fmaf(v[6].x, w6, f0);   f1 = fmaf(v[6].y, w6, f1);
    f0 = fmaf(v[7].x, w7, f0);   f1 = fmaf(v[7].y, w7, f1);
}

__global__ void __launch_bounds__(THREADS)
hashgrid_kernel(const float* __restrict__ xin,
                const float* __restrict__ table,
                const float* __restrict__ mask,
                float* __restrict__ out,
                int n)
{
    __shared__ float sx[PTS * 3];
    __shared__ float tile[PTS * TILE_STRIDE];
    __shared__ int s_act[17];          // [0]=count, [1..16]=active level ids

    const int tid = threadIdx.x;
    const size_t p0 = (size_t)blockIdx.x * PTS;

    // Coords, zero-padded past n so all lanes compute harmless in-bounds gathers.
    if (tid < PTS * 3) {
        const size_t gi = p0 * 3 + tid;
        sx[tid] = (gi < (size_t)n * 3) ? xin[gi] : 0.f;
    }
    if (tid == 0) {
        int c = 0;
#pragma unroll
        for (int l = 0; l < 16; l++) {
            if (__ldg(mask + 2 * l) != 0.f || __ldg(mask + 2 * l + 1) != 0.f)
                s_act[1 + c++] = l;
        }
        s_act[0] = c;
    }
#pragma unroll
    for (int i = tid; i < PTS * TILE_STRIDE; i += THREADS) tile[i] = 0.f;
    __syncthreads();

    const int warp = tid >> 5;
    const int lane = tid & 31;
    const int nact = s_act[0];

    const int pA = lane;            // point A within block
    const int pB = lane + 32;       // point B within block
    const float axp = sx[pA * 3 + 0], ayp = sx[pA * 3 + 1], azp = sx[pA * 3 + 2];
    const float bxp = sx[pB * 3 + 0], byp = sx[pB * 3 + 1], bzp = sx[pB * 3 + 2];

    for (int a = warp; a < nact; a += NWARPS) {
        const int lv = s_act[1 + a];
        const int res = c_res[lv];
        const float2* __restrict__ tbl =
            reinterpret_cast<const float2*>(table) + (size_t)lv * TSIZE;

        // Phase 1: index math for BOTH points.
        uint32_t ia[8], ib[8];
        float wxa, wya, wza, wxb, wyb, wzb;
        corner_indices(lv, res, axp, ayp, azp, ia, wxa, wya, wza);
        corner_indices(lv, res, bxp, byp, bzp, ib, wxb, wyb, wzb);

        // Phase 2: issue ALL gathers (up to 16 loads in flight) before consuming.
        float2 va[8], vb[8];
        load_pair(tbl, ia[0], ia[1], va[0], va[1]);
        load_pair(tbl, ia[2], ia[3], va[2], va[3]);
        load_pair(tbl, ia[4], ia[5], va[4], va[5]);
        load_pair(tbl, ia[6], ia[7], va[6], va[7]);
        load_pair(tbl, ib[0], ib[1], vb[0], vb[1]);
        load_pair(tbl, ib[2], ib[3], vb[2], vb[3]);
        load_pair(tbl, ib[4], ib[5], vb[4], vb[5]);
        load_pair(tbl, ib[6], ib[7], vb[6], vb[7]);

        // Phase 3: consume.
        const float m0 = __ldg(mask + 2 * lv);
        const float m1 = __ldg(mask + 2 * lv + 1);
        float f0, f1;
        trilerp(va, wxa, wya, wza, f0, f1);
        tile[pA * TILE_STRIDE + 2 * lv]     = f0 * m0;
        tile[pA * TILE_STRIDE + 2 * lv + 1] = f1 * m1;
        trilerp(vb, wxb, wyb, wzb, f0, f1);
        tile[pB * TILE_STRIDE + 2 * lv]     = f0 * m0;
        tile[pB * TILE_STRIDE + 2 * lv + 1] = f1 * m1;
    }

    __syncthreads();

    // Coalesced streaming store: 64 points x 32 feats = 2048 floats = 512 float4.
    const size_t base_out = p0 * 32;
    const size_t lim = (size_t)n * 32;
#pragma unroll
    for (int k = 0; k < 2; k++) {
        const int e = k * 1024 + tid * 4;   // element within block tile [0, 2048)
        const int pp = e >> 5;
        const int f = e & 31;
        float4 v;
        v.x = tile[pp * TILE_STRIDE + f + 0];
        v.y = tile[pp * TILE_STRIDE + f + 1];
        v.z = tile[pp * TILE_STRIDE + f + 2];
        v.w = tile[pp * TILE_STRIDE + f + 3];
        const size_t gi = base_out + (size_t)e;
        if (gi < lim) {
            __stcs(reinterpret_cast<float4*>(out + gi), v);
        }
    }
}

extern "C" void kernel_launch(void* const* d_in, const int* in_sizes, int n_in,
                              void* d_out, int out_size) {
    const float* x     = (const float*)d_in[0];
    const float* table = (const float*)d_in[1];
    const float* mask  = (const float*)d_in[2];
    float* out = (float*)d_out;
    const int n = in_sizes[0] / 3;
    const int blocks = (n + PTS - 1) / PTS;
    hashgrid_kernel<<<blocks, THREADS>>>(x, table, mask, out, n);
}

// round 11
// speedup vs baseline: 1.0194x; 1.0194x over previous
#include <cuda_runtime.h>
#include <cstdint>

// ProgressiveBandHashGrid — R3 shape (warp-per-level, branchy hash fusion)
// + duplicated x-pair tables for the 5 dense levels: every dense x-corner
// pair becomes ONE aligned LDG.128, no parity branch.
//
// x:[N,3] f32, table:[16,2^19,2] f32, mask:[32] f32, out:[N,32] f32.
// Resolutions (reference fp64): 17 23 31 43 59 81 112 154 213 295 407 562 777
// 1073 1483 2049; dense iff res^3 <= 2^19 -> lv 0..4 dense.

#define THREADS 256
#define PTS 32           // points per block (one warp-lane each)
#define NWARPS 8
#define TILE_STRIDE 33   // 32 feats + 1 pad
#define TBITS 19
#define TSIZE (1u << TBITS)

// Duplicated dense tables, lv0..4 concatenated.
// entry e at level lv: cx + (res-1)*(cy + res*cz) -> (tbl[c], tbl[c+1])
// sizes (res-1)*res*res: 4624, 11638, 28830, 77658, 201898 ; total 324648.
#define DUP_TOTAL 324648
__device__ float4 g_dup[DUP_TOTAL];

__constant__ int c_res[16]  = {17, 23, 31, 43, 59, 81, 112, 154,
                               213, 295, 407, 562, 777, 1073, 1483, 2049};
__constant__ int c_dense[16] = {1, 1, 1, 1, 1, 0, 0, 0,
                                0, 0, 0, 0, 0, 0, 0, 0};
__constant__ int c_dupoff[5] = {0, 4624, 16262, 45092, 122750};
__constant__ int c_dupsy[5]  = {16, 22, 30, 42, 58};          // res-1
__constant__ int c_dupsz[5]  = {272, 506, 930, 1806, 3422};   // (res-1)*res

// ---------------- build kernel: fill g_dup from the raw table ----------------
template <int LV, int RES>
__device__ __forceinline__ void build_one(const float2* __restrict__ table, int e)
{
    const int rm1 = RES - 1;
    const int cx = e % rm1;
    const int rem = e / rm1;
    const int cy = rem % RES;
    const int cz = rem / RES;
    const float2* tbl = table + (size_t)LV * TSIZE;
    const int i0 = cx + RES * (cy + RES * cz);
    const float2 a = __ldg(tbl + i0);
    const float2 b = __ldg(tbl + i0 + 1);
    g_dup[c_dupoff[LV] + e] = make_float4(a.x, a.y, b.x, b.y);
}

__global__ void __launch_bounds__(256)
build_dup_kernel(const float* __restrict__ table)
{
    const int i = blockIdx.x * 256 + threadIdx.x;
    if (i >= DUP_TOTAL) return;
    const float2* t2 = reinterpret_cast<const float2*>(table);
    if      (i < 4624)   build_one<0, 17>(t2, i);
    else if (i < 16262)  build_one<1, 23>(t2, i - 4624);
    else if (i < 45092)  build_one<2, 31>(t2, i - 16262);
    else if (i < 122750) build_one<3, 43>(t2, i - 45092);
    else                 build_one<4, 59>(t2, i - 122750);
}

// ---------------- main kernel ----------------
// Hashed x-pair load: aligned adjacent -> one 16B load, else two 8B loads.
__device__ __forceinline__ void load_pair(const float2* __restrict__ tbl,
                                          uint32_t i0, uint32_t i1,
                                          float2& v0, float2& v1)
{
    if ((i0 ^ i1) == 1u) {
        const float4 q = __ldg(reinterpret_cast<const float4*>(tbl) + (i0 >> 1));
        if (i0 & 1u) { v0.x = q.z; v0.y = q.w; v1.x = q.x; v1.y = q.y; }
        else         { v0.x = q.x; v0.y = q.y; v1.x = q.z; v1.y = q.w; }
    } else {
        v0 = __ldg(tbl + i0);
        v1 = __ldg(tbl + i1);
    }
}

__global__ void __launch_bounds__(THREADS)
hashgrid_kernel(const float* __restrict__ xin,
                const float* __restrict__ table,
                const float* __restrict__ mask,
                float* __restrict__ out,
                int n)
{
    __shared__ float sx[PTS * 3];
    __shared__ float tile[PTS * TILE_STRIDE];
    __shared__ int s_act[17];          // [0]=count, [1..16]=active level ids

    const int tid = threadIdx.x;
    const size_t p0 = (size_t)blockIdx.x * PTS;

    if (tid < PTS * 3) {
        const size_t gi = p0 * 3 + tid;
        sx[tid] = (gi < (size_t)n * 3) ? xin[gi] : 0.f;
    }
    if (tid == 0) {
        int c = 0;
#pragma unroll
        for (int l = 0; l < 16; l++) {
            if (__ldg(mask + 2 * l) != 0.f || __ldg(mask + 2 * l + 1) != 0.f)
                s_act[1 + c++] = l;
        }
        s_act[0] = c;
    }
#pragma unroll
    for (int i = tid; i < PTS * TILE_STRIDE; i += THREADS) tile[i] = 0.f;
    __syncthreads();

    const int warp = tid >> 5;
    const int lane = tid & 31;
    const int nact = s_act[0];
    const bool valid = (p0 + (size_t)lane) < (size_t)n;

    const float px = sx[lane * 3 + 0];
    const float py = sx[lane * 3 + 1];
    const float pz = sx[lane * 3 + 2];

    for (int a = warp; a < nact; a += NWARPS) {
        const int lv = s_act[1 + a];
        if (!valid) continue;

        const int res = c_res[lv];
        const float scale = (float)(res - 1);
        const float fx = px * scale, fy = py * scale, fz = pz * scale;
        int cx = __float2int_rd(fx); cx = max(0, min(cx, res - 2));
        int cy = __float2int_rd(fy); cy = max(0, min(cy, res - 2));
        int cz = __float2int_rd(fz); cz = max(0, min(cz, res - 2));
        const float wx = fx - (float)cx;
        const float wy = fy - (float)cy;
        const float wz = fz - (float)cz;

        const float ux = 1.f - wx, uy = 1.f - wy, uz = 1.f - wz;
        const float y0z0 = uy * uz, y1z0 = wy * uz;
        const float y0z1 = uy * wz, y1z1 = wy * wz;
        const float w000 = ux * y0z0, w100 = wx * y0z0;
        const float w010 = ux * y1z0, w110 = wx * y1z0;
        const float w001 = ux * y0z1, w101 = wx * y0z1;
        const float w011 = ux * y1z1, w111 = wx * y1z1;

        float f0, f1;

        if (c_dense[lv]) {
            // 100% fused: 4 straight-line LDG.128 from the duplicated table.
            const float4* __restrict__ dtbl = g_dup + c_dupoff[lv];
            const uint32_t sy = (uint32_t)c_dupsy[lv];
            const uint32_t sz = (uint32_t)c_dupsz[lv];
            const uint32_t base = (uint32_t)cx + sy * (uint32_t)cy + sz * (uint32_t)cz;
            const float4 q00 = __ldg(dtbl + base);            // (v000, v100)
            const float4 q10 = __ldg(dtbl + base + sy);       // (v010, v110)
            const float4 q01 = __ldg(dtbl + base + sz);       // (v001, v101)
            const float4 q11 = __ldg(dtbl + base + sy + sz);  // (v011, v111)

            f0 = q00.x * w000;            f1 = q00.y * w000;
            f0 = fmaf(q00.z, w100, f0);   f1 = fmaf(q00.w, w100, f1);
            f0 = fmaf(q10.x, w010, f0);   f1 = fmaf(q10.y, w010, f1);
            f0 = fmaf(q10.z, w110, f0);   f1 = fmaf(q10.w, w110, f1);
            f0 = fmaf(q01.x, w001, f0);   f1 = fmaf(q01.y, w001, f1);
            f0 = fmaf(q01.z, w101, f0);   f1 = fmaf(q01.w, w101, f1);
            f0 = fmaf(q11.x, w011, f0);   f1 = fmaf(q11.y, w011, f1);
            f0 = fmaf(q11.z, w111, f0);   f1 = fmaf(q11.w, w111, f1);
        } else {
            const float2* __restrict__ tbl =
                reinterpret_cast<const float2*>(table) + (size_t)lv * TSIZE;
            const uint32_t P1 = 2654435761u, P2 = 805459861u;
            const uint32_t M = TSIZE - 1u;
            const uint32_t hx0 = (uint32_t)cx,      hx1 = hx0 + 1u;
            const uint32_t hy0 = (uint32_t)cy * P1, hy1 = hy0 + P1;
            const uint32_t hz0 = (uint32_t)cz * P2, hz1 = hz0 + P2;
            const uint32_t i000 = (hx0 ^ hy0 ^ hz0) & M, i100 = (hx1 ^ hy0 ^ hz0) & M;
            const uint32_t i010 = (hx0 ^ hy1 ^ hz0) & M, i110 = (hx1 ^ hy1 ^ hz0) & M;
            const uint32_t i001 = (hx0 ^ hy0 ^ hz1) & M, i101 = (hx1 ^ hy0 ^ hz1) & M;
            const uint32_t i011 = (hx0 ^ hy1 ^ hz1) & M, i111 = (hx1 ^ hy1 ^ hz1) & M;

            float2 v000, v100, v010, v110, v001, v101, v011, v111;
            load_pair(tbl, i000, i100, v000, v100);
            load_pair(tbl, i010, i110, v010, v110);
            load_pair(tbl, i001, i101, v001, v101);
            load_pair(tbl, i011, i111, v011, v111);

            f0 = v000.x * w000;             f1 = v000.y * w000;
            f0 = fmaf(v100.x, w100, f0);    f1 = fmaf(v100.y, w100, f1);
            f0 = fmaf(v010.x, w010, f0);    f1 = fmaf(v010.y, w010, f1);
            f0 = fmaf(v110.x, w110, f0);    f1 = fmaf(v110.y, w110, f1);
            f0 = fmaf(v001.x, w001, f0);    f1 = fmaf(v001.y, w001, f1);
            f0 = fmaf(v101.x, w101, f0);    f1 = fmaf(v101.y, w101, f1);
            f0 = fmaf(v011.x, w011, f0);    f1 = fmaf(v011.y, w011, f1);
            f0 = fmaf(v111.x, w111, f0);    f1 = fmaf(v111.y, w111, f1);
        }

        f0 *= __ldg(mask + 2 * lv);
        f1 *= __ldg(mask + 2 * lv + 1);

        tile[lane * TILE_STRIDE + 2 * lv]     = f0;   // distinct lv per warp: no race
        tile[lane * TILE_STRIDE + 2 * lv + 1] = f1;
    }

    __syncthreads();

    // Coalesced streaming store: 32 points x 32 feats = 1024 floats = 256 x float4.
    const size_t base_out = p0 * 32;
    const size_t lim = (size_t)n * 32;
    const int e = tid * 4;
    const int pp = e >> 5;
    const int f = e & 31;
    float4 v;
    v.x = tile[pp * TILE_STRIDE + f + 0];
    v.y = tile[pp * TILE_STRIDE + f + 1];
    v.z = tile[pp * TILE_STRIDE + f + 2];
    v.w = tile[pp * TILE_STRIDE + f + 3];
    const size_t gi = base_out + (size_t)e;
    if (gi < lim) {
        __stcs(reinterpret_cast<float4*>(out + gi), v);
    }
}

extern "C" void kernel_launch(void* const* d_in, const int* in_sizes, int n_in,
                              void* d_out, int out_size) {
    const float* x     = (const float*)d_in[0];
    const float* table = (const float*)d_in[1];
    const float* mask  = (const float*)d_in[2];
    float* out = (float*)d_out;
    const int n = in_sizes[0] / 3;

    build_dup_kernel<<<(DUP_TOTAL + 255) / 256, 256>>>(table);

    const int blocks = (n + PTS - 1) / PTS;
    hashgrid_kernel<<<blocks, THREADS>>>(x, table, mask, out, n);
}

// round 12
// speedup vs baseline: 1.0791x; 1.0586x over previous
#include <cuda_runtime.h>
#include <cstdint>

// ProgressiveBandHashGrid — warp-per-level + dense dup-table (all dense x-pairs
// load as one aligned LDG.128) + __launch_bounds__(256,6) to hold 6 blocks/SM.
//
// x:[N,3] f32, table:[16,2^19,2] f32, mask:[32] f32, out:[N,32] f32.
// Resolutions (reference fp64): 17 23 31 43 59 81 112 154 213 295 407 562 777
// 1073 1483 2049; dense iff res^3 <= 2^19 -> lv 0..4 dense.

#define THREADS 256
#define PTS 32           // points per block (one warp-lane each)
#define NWARPS 8
#define TILE_STRIDE 33   // 32 feats + 1 pad
#define TBITS 19
#define TSIZE (1u << TBITS)

// Duplicated dense tables, lv0..4 concatenated.
// entry e at level lv: cx + (res-1)*(cy + res*cz) -> (tbl[c], tbl[c+1])
// sizes (res-1)*res*res: 4624, 11638, 28830, 77658, 201898 ; total 324648.
#define DUP_TOTAL 324648
__device__ float4 g_dup[DUP_TOTAL];

__constant__ int c_res[16]  = {17, 23, 31, 43, 59, 81, 112, 154,
                               213, 295, 407, 562, 777, 1073, 1483, 2049};
__constant__ int c_dense[16] = {1, 1, 1, 1, 1, 0, 0, 0,
                                0, 0, 0, 0, 0, 0, 0, 0};
__constant__ int c_dupoff[5] = {0, 4624, 16262, 45092, 122750};
__constant__ int c_dupsy[5]  = {16, 22, 30, 42, 58};          // res-1
__constant__ int c_dupsz[5]  = {272, 506, 930, 1806, 3422};   // (res-1)*res

// ---------------- build kernel: fill g_dup from the raw table ----------------
template <int LV, int RES>
__device__ __forceinline__ void build_one(const float2* __restrict__ table, int e)
{
    const int rm1 = RES - 1;
    const int cx = e % rm1;
    const int rem = e / rm1;
    const int cy = rem % RES;
    const int cz = rem / RES;
    const float2* tbl = table + (size_t)LV * TSIZE;
    const int i0 = cx + RES * (cy + RES * cz);
    const float2 a = __ldg(tbl + i0);
    const float2 b = __ldg(tbl + i0 + 1);
    g_dup[c_dupoff[LV] + e] = make_float4(a.x, a.y, b.x, b.y);
}

__global__ void __launch_bounds__(256)
build_dup_kernel(const float* __restrict__ table)
{
    const int i = blockIdx.x * 256 + threadIdx.x;
    if (i >= DUP_TOTAL) return;
    const float2* t2 = reinterpret_cast<const float2*>(table);
    if      (i < 4624)   build_one<0, 17>(t2, i);
    else if (i < 16262)  build_one<1, 23>(t2, i - 4624);
    else if (i < 45092)  build_one<2, 31>(t2, i - 16262);
    else if (i < 122750) build_one<3, 43>(t2, i - 45092);
    else                 build_one<4, 59>(t2, i - 122750);
}

// ---------------- main kernel ----------------
// Hashed x-pair load: aligned adjacent -> one 16B load, else two 8B loads.
__device__ __forceinline__ void load_pair(const float2* __restrict__ tbl,
                                          uint32_t i0, uint32_t i1,
                                          float2& v0, float2& v1)
{
    if ((i0 ^ i1) == 1u) {
        const float4 q = __ldg(reinterpret_cast<const float4*>(tbl) + (i0 >> 1));
        if (i0 & 1u) { v0.x = q.z; v0.y = q.w; v1.x = q.x; v1.y = q.y; }
        else         { v0.x = q.x; v0.y = q.y; v1.x = q.z; v1.y = q.w; }
    } else {
        v0 = __ldg(tbl + i0);
        v1 = __ldg(tbl + i1);
    }
}

__global__ void __launch_bounds__(THREADS, 6)
hashgrid_kernel(const float* __restrict__ xin,
                const float* __restrict__ table,
                const float* __restrict__ mask,
                float* __restrict__ out,
                int n)
{
    __shared__ float sx[PTS * 3];
    __shared__ float tile[PTS * TILE_STRIDE];
    __shared__ int s_act[17];          // [0]=count, [1..16]=active level ids

    const int tid = threadIdx.x;
    const size_t p0 = (size_t)blockIdx.x * PTS;

    // Coords, zero-padded past n: tail lanes compute harmless in-bounds gathers.
    if (tid < PTS * 3) {
        const size_t gi = p0 * 3 + tid;
        sx[tid] = (gi < (size_t)n * 3) ? xin[gi] : 0.f;
    }
    if (tid == 0) {
        int c = 0;
#pragma unroll
        for (int l = 0; l < 16; l++) {
            if (__ldg(mask + 2 * l) != 0.f || __ldg(mask + 2 * l + 1) != 0.f)
                s_act[1 + c++] = l;
        }
        s_act[0] = c;
    }
#pragma unroll
    for (int i = tid; i < PTS * TILE_STRIDE; i += THREADS) tile[i] = 0.f;
    __syncthreads();

    const int warp = tid >> 5;
    const int lane = tid & 31;
    const int nact = s_act[0];

    const float px = sx[lane * 3 + 0];
    const float py = sx[lane * 3 + 1];
    const float pz = sx[lane * 3 + 2];

    for (int a = warp; a < nact; a += NWARPS) {
        const int lv = s_act[1 + a];

        const int res = c_res[lv];
        const float scale = (float)(res - 1);
        const float fx = px * scale, fy = py * scale, fz = pz * scale;
        int cx = __float2int_rd(fx); cx = max(0, min(cx, res - 2));
        int cy = __float2int_rd(fy); cy = max(0, min(cy, res - 2));
        int cz = __float2int_rd(fz); cz = max(0, min(cz, res - 2));
        const float wx = fx - (float)cx;
        const float wy = fy - (float)cy;
        const float wz = fz - (float)cz;

        const float ux = 1.f - wx, uy = 1.f - wy, uz = 1.f - wz;
        const float y0z0 = uy * uz, y1z0 = wy * uz;
        const float y0z1 = uy * wz, y1z1 = wy * wz;
        const float w000 = ux * y0z0, w100 = wx * y0z0;
        const float w010 = ux * y1z0, w110 = wx * y1z0;
        const float w001 = ux * y0z1, w101 = wx * y0z1;
        const float w011 = ux * y1z1, w111 = wx * y1z1;

        float f0, f1;

        if (c_dense[lv]) {
            // 100% fused: 4 straight-line LDG.128 from the duplicated table.
            const float4* __restrict__ dtbl = g_dup + c_dupoff[lv];
            const uint32_t sy = (uint32_t)c_dupsy[lv];
            const uint32_t sz = (uint32_t)c_dupsz[lv];
            const uint32_t base = (uint32_t)cx + sy * (uint32_t)cy + sz * (uint32_t)cz;
            const float4 q00 = __ldg(dtbl + base);            // (v000, v100)
            const float4 q10 = __ldg(dtbl + base + sy);       // (v010, v110)
            const float4 q01 = __ldg(dtbl + base + sz);       // (v001, v101)
            const float4 q11 = __ldg(dtbl + base + sy + sz);  // (v011, v111)

            f0 = q00.x * w000;            f1 = q00.y * w000;
            f0 = fmaf(q00.z, w100, f0);   f1 = fmaf(q00.w, w100, f1);
            f0 = fmaf(q10.x, w010, f0);   f1 = fmaf(q10.y, w010, f1);
            f0 = fmaf(q10.z, w110, f0);   f1 = fmaf(q10.w, w110, f1);
            f0 = fmaf(q01.x, w001, f0);   f1 = fmaf(q01.y, w001, f1);
            f0 = fmaf(q01.z, w101, f0);   f1 = fmaf(q01.w, w101, f1);
            f0 = fmaf(q11.x, w011, f0);   f1 = fmaf(q11.y, w011, f1);
            f0 = fmaf(q11.z, w111, f0);   f1 = fmaf(q11.w, w111, f1);
        } else {
            const float2* __restrict__ tbl =
                reinterpret_cast<const float2*>(table) + (size_t)lv * TSIZE;
            const uint32_t P1 = 2654435761u, P2 = 805459861u;
            const uint32_t M = TSIZE - 1u;
            const uint32_t hx0 = (uint32_t)cx,      hx1 = hx0 + 1u;
            const uint32_t hy0 = (uint32_t)cy * P1, hy1 = hy0 + P1;
            const uint32_t hz0 = (uint32_t)cz * P2, hz1 = hz0 + P2;
            const uint32_t i000 = (hx0 ^ hy0 ^ hz0) & M, i100 = (hx1 ^ hy0 ^ hz0) & M;
            const uint32_t i010 = (hx0 ^ hy1 ^ hz0) & M, i110 = (hx1 ^ hy1 ^ hz0) & M;
            const uint32_t i001 = (hx0 ^ hy0 ^ hz1) & M, i101 = (hx1 ^ hy0 ^ hz1) & M;
            const uint32_t i011 = (hx0 ^ hy1 ^ hz1) & M, i111 = (hx1 ^ hy1 ^ hz1) & M;

            float2 v000, v100, v010, v110, v001, v101, v011, v111;
            load_pair(tbl, i000, i100, v000, v100);
            load_pair(tbl, i010, i110, v010, v110);
            load_pair(tbl, i001, i101, v001, v101);
            load_pair(tbl, i011, i111, v011, v111);

            f0 = v000.x * w000;             f1 = v000.y * w000;
            f0 = fmaf(v100.x, w100, f0);    f1 = fmaf(v100.y, w100, f1);
            f0 = fmaf(v010.x, w010, f0);    f1 = fmaf(v010.y, w010, f1);
            f0 = fmaf(v110.x, w110, f0);    f1 = fmaf(v110.y, w110, f1);
            f0 = fmaf(v001.x, w001, f0);    f1 = fmaf(v001.y, w001, f1);
            f0 = fmaf(v101.x, w101, f0);    f1 = fmaf(v101.y, w101, f1);
            f0 = fmaf(v011.x, w011, f0);    f1 = fmaf(v011.y, w011, f1);
            f0 = fmaf(v111.x, w111, f0);    f1 = fmaf(v111.y, w111, f1);
        }

        f0 *= __ldg(mask + 2 * lv);
        f1 *= __ldg(mask + 2 * lv + 1);

        tile[lane * TILE_STRIDE + 2 * lv]     = f0;   // distinct lv per warp: no race
        tile[lane * TILE_STRIDE + 2 * lv + 1] = f1;
    }

    __syncthreads();

    // Coalesced streaming store: 32 points x 32 feats = 1024 floats = 256 x float4.
    const size_t base_out = p0 * 32;
    const size_t lim = (size_t)n * 32;
    const int e = tid * 4;
    const int pp = e >> 5;
    const int f = e & 31;
    float4 v;
    v.x = tile[pp * TILE_STRIDE + f + 0];
    v.y = tile[pp * TILE_STRIDE + f + 1];
    v.z = tile[pp * TILE_STRIDE + f + 2];
    v.w = tile[pp * TILE_STRIDE + f + 3];
    const size_t gi = base_out + (size_t)e;
    if (gi < lim) {
        __stcs(reinterpret_cast<float4*>(out + gi), v);
    }
}

extern "C" void kernel_launch(void* const* d_in, const int* in_sizes, int n_in,
                              void* d_out, int out_size) {
    const float* x     = (const float*)d_in[0];
    const float* table = (const float*)d_in[1];
    const float* mask  = (const float*)d_in[2];
    float* out = (float*)d_out;
    const int n = in_sizes[0] / 3;

    build_dup_kernel<<<(DUP_TOTAL + 255) / 256, 256>>>(table);

    const int blocks = (n + PTS - 1) / PTS;
    hashgrid_kernel<<<blocks, THREADS>>>(x, table, mask, out, n);
}

// round 16
// speedup vs baseline: 1.2653x; 1.1725x over previous
#include <cuda_runtime.h>
#include <cstdint>

// ProgressiveBandHashGrid — warp-per-level + dense dup-table, with per-block
// overhead amputated: mask compaction hoisted to a pre-pass, coord smem stage
// and its barrier removed (one __syncthreads left, before the transpose store).
//
// x:[N,3] f32, table:[16,2^19,2] f32, mask:[32] f32, out:[N,32] f32.
// Resolutions (reference fp64): 17 23 31 43 59 81 112 154 213 295 407 562 777
// 1073 1483 2049; dense iff res^3 <= 2^19 -> lv 0..4 dense.

#define THREADS 256
#define PTS 32           // points per block (one warp-lane each)
#define NWARPS 8
#define TILE_STRIDE 33   // 32 feats + 1 pad
#define TBITS 19
#define TSIZE (1u << TBITS)

// Duplicated dense tables, lv0..4 concatenated.
// entry e at level lv: cx + (res-1)*(cy + res*cz) -> (tbl[c], tbl[c+1])
// sizes (res-1)*res*res: 4624, 11638, 28830, 77658, 201898 ; total 324648.
#define DUP_TOTAL 324648
__device__ float4 g_dup[DUP_TOTAL];

// Precomputed active-level list (from mask), built once per launch.
__device__ int    g_nact;
__device__ int    g_actlv[16];
__device__ float2 g_actmask[16];

__constant__ int c_res[16]  = {17, 23, 31, 43, 59, 81, 112, 154,
                               213, 295, 407, 562, 777, 1073, 1483, 2049};
__constant__ int c_dense[16] = {1, 1, 1, 1, 1, 0, 0, 0,
                                0, 0, 0, 0, 0, 0, 0, 0};
__constant__ int c_dupoff[5] = {0, 4624, 16262, 45092, 122750};
__constant__ int c_dupsy[5]  = {16, 22, 30, 42, 58};          // res-1
__constant__ int c_dupsz[5]  = {272, 506, 930, 1806, 3422};   // (res-1)*res

// ---------------- pre-pass 1: compact the mask into an active-level list ----
__global__ void mask_compact_kernel(const float* __restrict__ mask)
{
    if (threadIdx.x == 0 && blockIdx.x == 0) {
        int c = 0;
#pragma unroll
        for (int l = 0; l < 16; l++) {
            const float m0 = mask[2 * l], m1 = mask[2 * l + 1];
            if (m0 != 0.f || m1 != 0.f) {
                g_actlv[c] = l;
                g_actmask[c] = make_float2(m0, m1);
                c++;
            }
        }
        g_nact = c;
    }
}

// ---------------- pre-pass 2: fill g_dup from the raw table -----------------
template <int LV, int RES>
__device__ __forceinline__ void build_one(const float2* __restrict__ table, int e)
{
    const int rm1 = RES - 1;
    const int cx = e % rm1;
    const int rem = e / rm1;
    const int cy = rem % RES;
    const int cz = rem / RES;
    const float2* tbl = table + (size_t)LV * TSIZE;
    const int i0 = cx + RES * (cy + RES * cz);
    const float2 a = __ldg(tbl + i0);
    const float2 b = __ldg(tbl + i0 + 1);
    g_dup[c_dupoff[LV] + e] = make_float4(a.x, a.y, b.x, b.y);
}

__global__ void __launch_bounds__(256)
build_dup_kernel(const float* __restrict__ table)
{
    const int i = blockIdx.x * 256 + threadIdx.x;
    if (i >= DUP_TOTAL) return;
    const float2* t2 = reinterpret_cast<const float2*>(table);
    if      (i < 4624)   build_one<0, 17>(t2, i);
    else if (i < 16262)  build_one<1, 23>(t2, i - 4624);
    else if (i < 45092)  build_one<2, 31>(t2, i - 16262);
    else if (i < 122750) build_one<3, 43>(t2, i - 45092);
    else                 build_one<4, 59>(t2, i - 122750);
}

// ---------------- main kernel ----------------
// Hashed x-pair load: aligned adjacent -> one 16B load, else two 8B loads.
__device__ __forceinline__ void load_pair(const float2* __restrict__ tbl,
                                          uint32_t i0, uint32_t i1,
                                          float2& v0, float2& v1)
{
    if ((i0 ^ i1) == 1u) {
        const float4 q = __ldg(reinterpret_cast<const float4*>(tbl) + (i0 >> 1));
        if (i0 & 1u) { v0.x = q.z; v0.y = q.w; v1.x = q.x; v1.y = q.y; }
        else         { v0.x = q.x; v0.y = q.y; v1.x = q.z; v1.y = q.w; }
    } else {
        v0 = __ldg(tbl + i0);
        v1 = __ldg(tbl + i1);
    }
}

__global__ void __launch_bounds__(THREADS, 6)
hashgrid_kernel(const float* __restrict__ xin,
                const float* __restrict__ table,
                float* __restrict__ out,
                int n)
{
    __shared__ float tile[PTS * TILE_STRIDE];

    const int tid = threadIdx.x;
    const int warp = tid >> 5;
    const int lane = tid & 31;
    const size_t p0 = (size_t)blockIdx.x * PTS;

    // Zero the output tile (inactive levels stay zero).
#pragma unroll
    for (int i = tid; i < PTS * TILE_STRIDE; i += THREADS) tile[i] = 0.f;

    // Each lane reads its own point directly (clamped; tail guarded at store).
    const int p = max(0, min((int)(p0 + (size_t)lane), n - 1));
    const float px = __ldg(xin + 3 * p + 0);
    const float py = __ldg(xin + 3 * p + 1);
    const float pz = __ldg(xin + 3 * p + 2);

    const int nact = g_nact;

    for (int a = warp; a < nact; a += NWARPS) {
        const int lv = g_actlv[a];
        const float2 m = g_actmask[a];

        const int res = c_res[lv];
        const float scale = (float)(res - 1);
        const float fx = px * scale, fy = py * scale, fz = pz * scale;
        int cx = __float2int_rd(fx); cx = max(0, min(cx, res - 2));
        int cy = __float2int_rd(fy); cy = max(0, min(cy, res - 2));
        int cz = __float2int_rd(fz); cz = max(0, min(cz, res - 2));
        const float wx = fx - (float)cx;
        const float wy = fy - (float)cy;
        const float wz = fz - (float)cz;

        const float ux = 1.f - wx, uy = 1.f - wy, uz = 1.f - wz;
        const float y0z0 = uy * uz, y1z0 = wy * uz;
        const float y0z1 = uy * wz, y1z1 = wy * wz;
        const float w000 = ux * y0z0, w100 = wx * y0z0;
        const float w010 = ux * y1z0, w110 = wx * y1z0;
        const float w001 = ux * y0z1, w101 = wx * y0z1;
        const float w011 = ux * y1z1, w111 = wx * y1z1;

        float f0, f1;

        if (c_dense[lv]) {
            // 100% fused: 4 straight-line LDG.128 from the duplicated table.
            const float4* __restrict__ dtbl = g_dup + c_dupoff[lv];
            const uint32_t sy = (uint32_t)c_dupsy[lv];
            const uint32_t sz = (uint32_t)c_dupsz[lv];
            const uint32_t base = (uint32_t)cx + sy * (uint32_t)cy + sz * (uint32_t)cz;
            const float4 q00 = __ldg(dtbl + base);            // (v000, v100)
            const float4 q10 = __ldg(dtbl + base + sy);       // (v010, v110)
            const float4 q01 = __ldg(dtbl + base + sz);       // (v001, v101)
            const float4 q11 = __ldg(dtbl + base + sy + sz);  // (v011, v111)

            f0 = q00.x * w000;            f1 = q00.y * w000;
            f0 = fmaf(q00.z, w100, f0);   f1 = fmaf(q00.w, w100, f1);
            f0 = fmaf(q10.x, w010, f0);   f1 = fmaf(q10.y, w010, f1);
            f0 = fmaf(q10.z, w110, f0);   f1 = fmaf(q10.w, w110, f1);
            f0 = fmaf(q01.x, w001, f0);   f1 = fmaf(q01.y, w001, f1);
            f0 = fmaf(q01.z, w101, f0);   f1 = fmaf(q01.w, w101, f1);
            f0 = fmaf(q11.x, w011, f0);   f1 = fmaf(q11.y, w011, f1);
            f0 = fmaf(q11.z, w111, f0);   f1 = fmaf(q11.w, w111, f1);
        } else {
            const float2* __restrict__ tbl =
                reinterpret_cast<const float2*>(table) + (size_t)lv * TSIZE;
            const uint32_t P1 = 2654435761u, P2 = 805459861u;
            const uint32_t M = TSIZE - 1u;
            const uint32_t hx0 = (uint32_t)cx,      hx1 = hx0 + 1u;
            const uint32_t hy0 = (uint32_t)cy * P1, hy1 = hy0 + P1;
            const uint32_t hz0 = (uint32_t)cz * P2, hz1 = hz0 + P2;
            const uint32_t i000 = (hx0 ^ hy0 ^ hz0) & M, i100 = (hx1 ^ hy0 ^ hz0) & M;
            const uint32_t i010 = (hx0 ^ hy1 ^ hz0) & M, i110 = (hx1 ^ hy1 ^ hz0) & M;
            const uint32_t i001 = (hx0 ^ hy0 ^ hz1) & M, i101 = (hx1 ^ hy0 ^ hz1) & M;
            const uint32_t i011 = (hx0 ^ hy1 ^ hz1) & M, i111 = (hx1 ^ hy1 ^ hz1) & M;

            float2 v000, v100, v010, v110, v001, v101, v011, v111;
            load_pair(tbl, i000, i100, v000, v100);
            load_pair(tbl, i010, i110, v010, v110);
            load_pair(tbl, i001, i101, v001, v101);
            load_pair(tbl, i011, i111, v011, v111);

            f0 = v000.x * w000;             f1 = v000.y * w000;
            f0 = fmaf(v100.x, w100, f0);    f1 = fmaf(v100.y, w100, f1);
            f0 = fmaf(v010.x, w010, f0);    f1 = fmaf(v010.y, w010, f1);
            f0 = fmaf(v110.x, w110, f0);    f1 = fmaf(v110.y, w110, f1);
            f0 = fmaf(v001.x, w001, f0);    f1 = fmaf(v001.y, w001, f1);
            f0 = fmaf(v101.x, w101, f0);    f1 = fmaf(v101.y, w101, f1);
            f0 = fmaf(v011.x, w011, f0);    f1 = fmaf(v011.y, w011, f1);
            f0 = fmaf(v111.x, w111, f0);    f1 = fmaf(v111.y, w111, f1);
        }

        tile[lane * TILE_STRIDE + 2 * lv]     = f0 * m.x;   // distinct lv per warp
        tile[lane * TILE_STRIDE + 2 * lv + 1] = f1 * m.y;
    }

    __syncthreads();

    // Coalesced streaming store: 32 points x 32 feats = 1024 floats = 256 x float4.
    const size_t base_out = p0 * 32;
    const size_t lim = (size_t)n * 32;
    const int e = tid * 4;
    const int pp = e >> 5;
    const int f = e & 31;
    float4 v;
    v.x = tile[pp * TILE_STRIDE + f + 0];
    v.y = tile[pp * TILE_STRIDE + f + 1];
    v.z = tile[pp * TILE_STRIDE + f + 2];
    v.w = tile[pp * TILE_STRIDE + f + 3];
    const size_t gi = base_out + (size_t)e;
    if (gi < lim) {
        __stcs(reinterpret_cast<float4*>(out + gi), v);
    }
}

extern "C" void kernel_launch(void* const* d_in, const int* in_sizes, int n_in,
                              void* d_out, int out_size) {
    const float* x     = (const float*)d_in[0];
    const float* table = (const float*)d_in[1];
    const float* mask  = (const float*)d_in[2];
    float* out = (float*)d_out;
    const int n = in_sizes[0] / 3;

    mask_compact_kernel<<<1, 1>>>(mask);
    build_dup_kernel<<<(DUP_TOTAL + 255) / 256, 256>>>(table);

    const int blocks = (n + PTS - 1) / PTS;
    hashgrid_kernel<<<blocks, THREADS>>>(x, table, out, n);
}